// round 1
// baseline (speedup 1.0000x reference)
#include <cuda_runtime.h>
#include <math_constants.h>

// Problem constants
#define BB   4
#define TT   4096
#define DIN  1024
#define HH   64

#define MROWS (BB * TT)        // 16384

// Scratch for projected q, k, v  (each 4 MB)
__device__ float g_q[MROWS * HH];
__device__ float g_k[MROWS * HH];
__device__ float g_v[MROWS * HH];

// ---------------------------------------------------------------------------
// Kernel 1: projections.  out[m][n] = sum_k x[m][k] * W[n][k] + b[n]
// grid = (MROWS/64, 3), block = 256 (16x16), 4x4 microtile per thread.
// ---------------------------------------------------------------------------
__global__ __launch_bounds__(256) void proj_kernel(
    const float* __restrict__ x,
    const float* __restrict__ Wq, const float* __restrict__ bq,
    const float* __restrict__ Wk, const float* __restrict__ bk,
    const float* __restrict__ Wv, const float* __restrict__ bv)
{
    __shared__ float Xs[32 * 65];   // Xs[k][m], padded
    __shared__ float Ws[32 * 65];   // Ws[k][n], padded

    const float* W;
    const float* bias;
    float* outp;
    if (blockIdx.y == 0)      { W = Wq; bias = bq; outp = g_q; }
    else if (blockIdx.y == 1) { W = Wk; bias = bk; outp = g_k; }
    else                      { W = Wv; bias = bv; outp = g_v; }

    const int m0  = blockIdx.x * 64;
    const int tid = threadIdx.x;
    const int tx  = tid & 15;
    const int ty  = tid >> 4;

    float acc[4][4];
#pragma unroll
    for (int i = 0; i < 4; ++i)
#pragma unroll
        for (int j = 0; j < 4; ++j) acc[i][j] = 0.f;

    for (int k0 = 0; k0 < DIN; k0 += 32) {
        __syncthreads();
#pragma unroll
        for (int e = tid; e < 64 * 32; e += 256) {
            int mm = e >> 5;      // 0..63
            int kk = e & 31;      // 0..31
            Xs[kk * 65 + mm] = x[(size_t)(m0 + mm) * DIN + k0 + kk];
            Ws[kk * 65 + mm] = W[(size_t)mm * DIN + k0 + kk];
        }
        __syncthreads();

#pragma unroll
        for (int kk = 0; kk < 32; ++kk) {
            float a[4], w[4];
#pragma unroll
            for (int i = 0; i < 4; ++i) a[i] = Xs[kk * 65 + ty * 4 + i];
#pragma unroll
            for (int j = 0; j < 4; ++j) w[j] = Ws[kk * 65 + tx * 4 + j];
#pragma unroll
            for (int i = 0; i < 4; ++i)
#pragma unroll
                for (int j = 0; j < 4; ++j) acc[i][j] += a[i] * w[j];
        }
    }

#pragma unroll
    for (int i = 0; i < 4; ++i)
#pragma unroll
        for (int j = 0; j < 4; ++j)
            outp[(size_t)(m0 + ty * 4 + i) * HH + tx * 4 + j] =
                acc[i][j] + bias[tx * 4 + j];
}

// ---------------------------------------------------------------------------
// Kernel 2: causal flash attention.
//   A := k (attention "query" rows i),  Bm := q (keys, cols j),  V := v.
//   out[b,i,h] = sum_{j<=i} softmax_j(k_i . q_j) v[j,h]
// grid = (T/64, B), block = 256 (16x16). Each CTA: 64 rows x 64 head dims.
// S tile (64x64) staged in smem, aliased over the Bs buffer.
// ---------------------------------------------------------------------------
#define TPAD 65
#define SMEM_FLOATS (3 * 64 * TPAD + 3 * 64)

__global__ __launch_bounds__(256) void attn_kernel(float* __restrict__ out)
{
    extern __shared__ float sm[];
    float* As  = sm;                    // 64 x 65  (k rows, fixed)
    float* Bs  = sm + 64 * TPAD;        // 64 x 65  (q tile; aliased as S/P tile)
    float* Vs  = sm + 2 * 64 * TPAD;    // 64 x 65  (v tile)
    float* m_s = sm + 3 * 64 * TPAD;    // 64 running max
    float* l_s = m_s + 64;              // 64 running sum
    float* sc_s= l_s + 64;              // 64 rescale factor

    const int it = (gridDim.x - 1) - blockIdx.x;   // heavy tiles first
    const int b  = blockIdx.y;
    const int tid = threadIdx.x;
    const int tx  = tid & 15;
    const int ty  = tid >> 4;

    const float* kbase = g_k + ((size_t)b * TT + it * 64) * HH;

    // load A tile (k rows)
#pragma unroll
    for (int e = tid; e < 64 * 64; e += 256) {
        int r = e >> 6, h = e & 63;
        As[r * TPAD + h] = kbase[r * HH + h];
    }
    if (tid < 64) { m_s[tid] = -CUDART_INF_F; l_s[tid] = 0.f; }

    float acc[4][4];
#pragma unroll
    for (int i = 0; i < 4; ++i)
#pragma unroll
        for (int j = 0; j < 4; ++j) acc[i][j] = 0.f;

    for (int jt = 0; jt <= it; ++jt) {
        __syncthreads();   // previous iter's reads of Bs(=P) / Vs done

        const float* qb = g_q + ((size_t)b * TT + jt * 64) * HH;
        const float* vb = g_v + ((size_t)b * TT + jt * 64) * HH;
#pragma unroll
        for (int e = tid; e < 64 * 64; e += 256) {
            int r = e >> 6, h = e & 63;
            Bs[r * TPAD + h] = qb[r * HH + h];
            Vs[r * TPAD + h] = vb[r * HH + h];
        }
        __syncthreads();

        // S = A . B^T   (4x4 per thread)
        float s[4][4];
#pragma unroll
        for (int i = 0; i < 4; ++i)
#pragma unroll
            for (int j = 0; j < 4; ++j) s[i][j] = 0.f;

#pragma unroll 8
        for (int h = 0; h < 64; ++h) {
            float a[4], qv[4];
#pragma unroll
            for (int i = 0; i < 4; ++i) a[i]  = As[(ty * 4 + i) * TPAD + h];
#pragma unroll
            for (int j = 0; j < 4; ++j) qv[j] = Bs[(tx * 4 + j) * TPAD + h];
#pragma unroll
            for (int i = 0; i < 4; ++i)
#pragma unroll
                for (int j = 0; j < 4; ++j) s[i][j] += a[i] * qv[j];
        }

        // causal mask on the diagonal tile
        if (jt == it) {
#pragma unroll
            for (int i = 0; i < 4; ++i)
#pragma unroll
                for (int j = 0; j < 4; ++j)
                    if (tx * 4 + j > ty * 4 + i) s[i][j] = -CUDART_INF_F;
        }

        __syncthreads();   // everyone finished reading Bs; safe to overwrite with S
#pragma unroll
        for (int i = 0; i < 4; ++i)
#pragma unroll
            for (int j = 0; j < 4; ++j)
                Bs[(ty * 4 + i) * TPAD + tx * 4 + j] = s[i][j];
        __syncthreads();

        // online softmax: 4 threads per row
        {
            const int row  = tid >> 2;
            const int quad = tid & 3;
            float mx = -CUDART_INF_F;
#pragma unroll
            for (int c = quad * 16; c < quad * 16 + 16; ++c)
                mx = fmaxf(mx, Bs[row * TPAD + c]);
            mx = fmaxf(mx, __shfl_xor_sync(0xffffffffu, mx, 1));
            mx = fmaxf(mx, __shfl_xor_sync(0xffffffffu, mx, 2));

            const float m_old = m_s[row];
            const float m_new = fmaxf(m_old, mx);

            float sum = 0.f;
#pragma unroll
            for (int c = quad * 16; c < quad * 16 + 16; ++c) {
                float p = expf(Bs[row * TPAD + c] - m_new);
                Bs[row * TPAD + c] = p;
                sum += p;
            }
            sum += __shfl_xor_sync(0xffffffffu, sum, 1);
            sum += __shfl_xor_sync(0xffffffffu, sum, 2);

            if (quad == 0) {
                float alpha = expf(m_old - m_new);
                sc_s[row] = alpha;
                l_s[row]  = l_s[row] * alpha + sum;
                m_s[row]  = m_new;
            }
        }
        __syncthreads();

        // rescale accumulators, then O += P . V
        float al[4];
#pragma unroll
        for (int i = 0; i < 4; ++i) al[i] = sc_s[ty * 4 + i];
#pragma unroll
        for (int i = 0; i < 4; ++i)
#pragma unroll
            for (int j = 0; j < 4; ++j) acc[i][j] *= al[i];

#pragma unroll 8
        for (int jj = 0; jj < 64; ++jj) {
            float p[4], vv[4];
#pragma unroll
            for (int i = 0; i < 4; ++i) p[i]  = Bs[(ty * 4 + i) * TPAD + jj];
#pragma unroll
            for (int j = 0; j < 4; ++j) vv[j] = Vs[jj * TPAD + tx * 4 + j];
#pragma unroll
            for (int i = 0; i < 4; ++i)
#pragma unroll
                for (int j = 0; j < 4; ++j) acc[i][j] += p[i] * vv[j];
        }
    }

    __syncthreads();
#pragma unroll
    for (int i = 0; i < 4; ++i) {
        const float inv_l = 1.0f / l_s[ty * 4 + i];
        const size_t rbase = ((size_t)b * TT + it * 64 + ty * 4 + i) * HH;
#pragma unroll
        for (int j = 0; j < 4; ++j)
            out[rbase + tx * 4 + j] = acc[i][j] * inv_l;
    }
}

// ---------------------------------------------------------------------------
extern "C" void kernel_launch(void* const* d_in, const int* in_sizes, int n_in,
                              void* d_out, int out_size)
{
    const float* x  = (const float*)d_in[0];
    const float* Wq = (const float*)d_in[1];
    const float* bq = (const float*)d_in[2];
    const float* Wk = (const float*)d_in[3];
    const float* bk = (const float*)d_in[4];
    const float* Wv = (const float*)d_in[5];
    const float* bv = (const float*)d_in[6];
    float* out = (float*)d_out;

    // Projections: q,k,v = x @ W^T + b
    proj_kernel<<<dim3(MROWS / 64, 3), 256>>>(x, Wq, bq, Wk, bk, Wv, bv);

    // Flash attention
    const int smem_bytes = SMEM_FLOATS * sizeof(float);   // 50,688 B
    cudaFuncSetAttribute(attn_kernel,
                         cudaFuncAttributeMaxDynamicSharedMemorySize,
                         smem_bytes);
    attn_kernel<<<dim3(TT / 64, BB), 256, smem_bytes>>>(out);
}